// round 12
// baseline (speedup 1.0000x reference)
#include <cuda_runtime.h>
#include <cuda_bf16.h>
#include <cstdint>

#define GAMMA 0.001f
#define NIMG 4096
#define MSUP 8192
#define KDIM 784
#define KPAD 800
#define NCLS 4

#define TI 128
#define TJ 128
#define KC 80
#define STA 88                 // padded smem row stride (elems): 176B, conflict-free
#define NSTAGE (KPAD / KC)     // 10
#define NJT (MSUP / TJ)        // 64
#define NIT (NIMG / TI)        // 32

#define CONV_BLOCKS NIMG           // 4096 (1 image per block, 224 active lanes)
#define PREP_BLOCKS (MSUP / 8)     // 1024

// ---- gemm dynamic smem layout (bytes) ----
#define BUF_BYTES (TI * STA * 2)         // 22528 per tile per buffer
#define OFF_A 0                          // 2 x 22528 = 45056
#define OFF_B 45056                      // 2 x 22528 = 45056
#define OFF_S2 90112                     // 512
#define OFF_F2 90624                     // 512
#define OFF_AL 91136                     // 2048
#define GEMM_SMEM 93184

// ---- device scratch (no allocs allowed) ----
__device__ __nv_bfloat16 g_featsB[NIMG * KPAD];
__device__ __nv_bfloat16 g_supB[MSUP * KPAD];
__device__ float g_s2[MSUP];
__device__ float g_f2[NIMG];
__device__ float g_part[NIMG * NCLS * NJT];   // transposed: [row*NCLS+c][jtile]

// ---------------------------------------------------------------------------
__device__ __forceinline__ uint32_t smem_u32(const void* p) {
    uint32_t a;
    asm("{ .reg .u64 t; cvta.to.shared.u64 t, %1; cvt.u32.u64 %0, t; }" : "=r"(a) : "l"(p));
    return a;
}
__device__ __forceinline__ void cp16(uint32_t smem, const void* gmem) {
    asm volatile("cp.async.cg.shared.global [%0], [%1], 16;" :: "r"(smem), "l"(gmem));
}
__device__ __forceinline__ void ldm_x4(uint32_t* r, uint32_t addr) {
    asm volatile("ldmatrix.sync.aligned.m8n8.x4.shared.b16 {%0,%1,%2,%3}, [%4];"
                 : "=r"(r[0]), "=r"(r[1]), "=r"(r[2]), "=r"(r[3]) : "r"(addr));
}
__device__ __forceinline__ void mma_bf16(float* d, const uint32_t* a, uint32_t b0, uint32_t b1) {
    asm volatile(
        "mma.sync.aligned.m16n8k16.row.col.f32.bf16.bf16.f32 "
        "{%0,%1,%2,%3}, {%4,%5,%6,%7}, {%8,%9}, {%0,%1,%2,%3};"
        : "+f"(d[0]), "+f"(d[1]), "+f"(d[2]), "+f"(d[3])
        : "r"(a[0]), "r"(a[1]), "r"(a[2]), "r"(a[3]), "r"(b0), "r"(b1));
}
__device__ __forceinline__ void ldw4(float* W, const float* base) {
    const float2* p = reinterpret_cast<const float2*>(base);
    float2 a = p[0], b = p[1];
    W[0] = a.x; W[1] = a.y; W[2] = b.x; W[3] = b.y;
}

// ---------------------------------------------------------------------------
// Merged preprocessing launch:
//   blocks [0, CONV_BLOCKS)            : conv, 1 image/block, 224 active lanes
//   blocks [CONV_BLOCKS, +PREP_BLOCKS) : support bf16 conversion + s2
// conv1: lane pairs split the 14 pooled rows 7/7 (symmetric, no divergence).
// conv2: lane pairs split the 8 input channels 4/4 + shfl_xor(1) combine.
// ---------------------------------------------------------------------------
__global__ void __launch_bounds__(256) pre_kernel(
    const float* __restrict__ x,
    const float* __restrict__ w1, const float* __restrict__ b1,
    const float* __restrict__ w2, const float* __restrict__ b2,
    const float* __restrict__ support)
{
    const int tid = threadIdx.x;

    if (blockIdx.x >= CONV_BLOCKS) {
        int row = (blockIdx.x - CONV_BLOCKS) * 8 + (tid >> 5);
        int lane = tid & 31;
        const float* src = support + (size_t)row * KDIM;
        __nv_bfloat16* dst = g_supB + (size_t)row * KPAD;
        float s = 0.f;
        for (int k = lane; k < KDIM; k += 32) {
            __nv_bfloat16 b = __float2bfloat16(src[k]);
            dst[k] = b;
            float v = __bfloat162float(b);
            s += v * v;
        }
        if (lane < KPAD - KDIM) dst[KDIM + lane] = __float2bfloat16(0.f);
        #pragma unroll
        for (int off = 16; off; off >>= 1) s += __shfl_xor_sync(0xffffffffu, s, off);
        if (lane == 0) g_s2[row] = s;
        return;
    }

    __shared__ float sx[900];             // 30x30 padded (+1)
    __shared__ float sp1[2048];           // 8 x 16x16 padded (+1)
    __shared__ float sw1[72], sb1[8], sw2[1152], sb2[16];
    __shared__ float sred[8];

    const int n = blockIdx.x;

    for (int i = tid; i < 900; i += 256) sx[i] = 0.f;
    for (int i = tid; i < 2048; i += 256) sp1[i] = 0.f;
    for (int i = tid; i < 72; i += 256) sw1[i] = w1[i];
    if (tid < 8) sb1[tid] = b1[tid];
    for (int i = tid; i < 1152; i += 256) sw2[i] = w2[i];
    if (tid < 16) sb2[tid] = b2[tid];
    __syncthreads();

    const float* xn = x + (size_t)n * 784;
    for (int i = tid; i < 784; i += 256) {
        int yy = i / 28, xx = i % 28;
        sx[(yy + 1) * 30 + xx + 1] = xn[i];
    }
    __syncthreads();

    // ---- conv1 + relu + pool: pair = (c 0..7, px 0..13), half = 7-py range ----
    if (tid < 224) {
        const int idx = tid >> 1, h = tid & 1;
        const int c = idx & 7, px = idx >> 3;
        const int py0 = h * 7;
        float w[9];
        #pragma unroll
        for (int k = 0; k < 9; k++) w[k] = sw1[c * 9 + k];
        const float bb = sb1[c];
        float W[4][4];
        #pragma unroll
        for (int pp = 0; pp < 7; pp++) {
            const int py = py0 + pp;
            if (pp == 0) {
                #pragma unroll
                for (int r = 0; r < 4; r++)
                    ldw4(W[r], sx + (2 * py + r) * 30 + 2 * px);
            } else {
                #pragma unroll
                for (int cc = 0; cc < 4; cc++) { W[0][cc] = W[2][cc]; W[1][cc] = W[3][cc]; }
                #pragma unroll
                for (int r = 2; r < 4; r++)
                    ldw4(W[r], sx + (2 * py + r) * 30 + 2 * px);
            }
            float m = 0.f;
            #pragma unroll
            for (int sy = 0; sy < 2; sy++)
                #pragma unroll
                for (int sxx = 0; sxx < 2; sxx++) {
                    float acc = bb;
                    #pragma unroll
                    for (int dy = 0; dy < 3; dy++)
                        #pragma unroll
                        for (int dx = 0; dx < 3; dx++)
                            acc += w[dy * 3 + dx] * W[sy + dy][sxx + dx];
                    m = fmaxf(m, fmaxf(acc, 0.f));
                }
            sp1[c * 256 + (py + 1) * 16 + px + 1] = m;
        }
    }
    __syncthreads();

    // ---- conv2 + relu + pool: pair = (c 0..15, px 0..6), half = 4-ic range ----
    float sq = 0.f;
    if (tid < 224) {
        const int idx = tid >> 1, h = tid & 1;
        const int px = idx % 7, c = idx / 7;
        float acc[7][4];
        const float bb = (h == 0) ? sb2[c] : 0.f;
        #pragma unroll
        for (int py = 0; py < 7; py++)
            #pragma unroll
            for (int q = 0; q < 4; q++) acc[py][q] = bb;

        #pragma unroll
        for (int ict = 0; ict < 4; ict++) {
            const int ic = h * 4 + ict;
            float w[9];
            #pragma unroll
            for (int k = 0; k < 9; k++) w[k] = sw2[c * 72 + ic * 9 + k];
            const float* sp = sp1 + ic * 256;
            float W[4][4];
            #pragma unroll
            for (int py = 0; py < 7; py++) {
                if (py == 0) {
                    #pragma unroll
                    for (int r = 0; r < 4; r++)
                        ldw4(W[r], sp + r * 16 + 2 * px);
                } else {
                    #pragma unroll
                    for (int cc = 0; cc < 4; cc++) { W[0][cc] = W[2][cc]; W[1][cc] = W[3][cc]; }
                    #pragma unroll
                    for (int r = 2; r < 4; r++)
                        ldw4(W[r], sp + (2 * py + r) * 16 + 2 * px);
                }
                #pragma unroll
                for (int sy = 0; sy < 2; sy++)
                    #pragma unroll
                    for (int sxx = 0; sxx < 2; sxx++) {
                        float a2 = 0.f;
                        #pragma unroll
                        for (int dy = 0; dy < 3; dy++)
                            #pragma unroll
                            for (int dx = 0; dx < 3; dx++)
                                a2 += w[dy * 3 + dx] * W[sy + dy][sxx + dx];
                        acc[py][sy * 2 + sxx] += a2;
                    }
            }
        }
        // combine the two ic-halves (adjacent lanes, identical control flow)
        #pragma unroll
        for (int py = 0; py < 7; py++)
            #pragma unroll
            for (int q = 0; q < 4; q++)
                acc[py][q] += __shfl_xor_sync(0xffffffffu, acc[py][q], 1);

        if (h == 0) {
            __nv_bfloat16* fdst = g_featsB + (size_t)n * KPAD + c * 49 + px;
            #pragma unroll
            for (int py = 0; py < 7; py++) {
                float m = 0.f;
                #pragma unroll
                for (int q = 0; q < 4; q++) m = fmaxf(m, fmaxf(acc[py][q], 0.f));
                __nv_bfloat16 bv = __float2bfloat16(m);
                fdst[py * 7] = bv;
                float fv = __bfloat162float(bv);
                sq += fv * fv;
            }
        }
    }
    if (tid < KPAD - KDIM)
        g_featsB[(size_t)n * KPAD + KDIM + tid] = __float2bfloat16(0.f);

    // f2 block reduction (8 warps)
    #pragma unroll
    for (int off = 16; off; off >>= 1) sq += __shfl_xor_sync(0xffffffffu, sq, off);
    if ((tid & 31) == 0) sred[tid >> 5] = sq;
    __syncthreads();
    if (tid == 0) {
        float s = 0.f;
        #pragma unroll
        for (int wv = 0; wv < 8; wv++) s += sred[wv];
        g_f2[n] = s;
    }
}

// ---------------------------------------------------------------------------
// bf16 mma.sync fused GEMM (R9/R11-proven): 128x128 CTA, KC=80, 10 stages,
// 2 smem buffers, register double-buffered fragments, 1 sync/stage.
// Partial store transposed: g_part[(row*NCLS+c)*NJT + jtile].
// ---------------------------------------------------------------------------
__global__ void __launch_bounds__(256, 2) gemm_mma(const float* __restrict__ alpha)
{
    extern __shared__ char dsm[];
    float* s2s = (float*)(dsm + OFF_S2);
    float* f2s = (float*)(dsm + OFF_F2);
    float4* als = (float4*)(dsm + OFF_AL);
    float* red = (float*)(dsm + OFF_A);   // reused after mainloop

    const int tid = threadIdx.x;
    const int lane = tid & 31, wid = tid >> 5;
    const int wi = wid >> 2;        // 0..1 : 64-row slice
    const int wj = wid & 3;         // 0..3 : 32-col slice
    const int ibase = blockIdx.x * TI;
    const int jbase = blockIdx.y * TJ;

    if (tid < TI) f2s[tid] = g_f2[ibase + tid];
    if (tid < TJ) {
        s2s[tid] = g_s2[jbase + tid];
        als[tid] = ((const float4*)alpha)[jbase + tid];
    }

    uint32_t aBase[2], bBase[2];
    #pragma unroll
    for (int b = 0; b < 2; b++) {
        aBase[b] = smem_u32(dsm + OFF_A + b * BUF_BYTES);
        bBase[b] = smem_u32(dsm + OFF_B + b * BUF_BYTES);
    }
    const __nv_bfloat16* gA = g_featsB + (size_t)ibase * KPAD;
    const __nv_bfloat16* gB = g_supB + (size_t)jbase * KPAD;

    float acc[4][4][4];
    #pragma unroll
    for (int mi = 0; mi < 4; mi++)
        #pragma unroll
        for (int nj = 0; nj < 4; nj++)
            #pragma unroll
            for (int e = 0; e < 4; e++) acc[mi][nj][e] = 0.f;

    auto prefetch = [&](int s, int b) {
        #pragma unroll
        for (int tcnt = 0; tcnt < 5; tcnt++) {
            int id = tid + tcnt * 256;
            int r = id / 10, c = id % 10;
            cp16(aBase[b] + (r * STA + c * 8) * 2, gA + (size_t)r * KPAD + s * KC + c * 8);
        }
        #pragma unroll
        for (int tcnt = 0; tcnt < 5; tcnt++) {
            int id = tid + tcnt * 256;
            int r = id / 10, c = id % 10;
            cp16(bBase[b] + (r * STA + c * 8) * 2, gB + (size_t)r * KPAD + s * KC + c * 8);
        }
        asm volatile("cp.async.commit_group;" ::: "memory");
    };

    prefetch(0, 0);

    const int a_row = (lane & 15);
    const int a_koff = (lane >> 4) * 8;
    const int b_nrow = ((lane >> 4) & 1) * 8 + (lane & 7);
    const int b_koff = ((lane >> 3) & 1) * 8;

    uint32_t afr[2][4][4], bfr[2][2][4];

    for (int s = 0; s < NSTAGE; s++) {
        asm volatile("cp.async.wait_group 0;" ::: "memory");
        __syncthreads();
        if (s + 1 < NSTAGE) prefetch(s + 1, (s + 1) & 1);

        const int b = s & 1;

        #pragma unroll
        for (int mi = 0; mi < 4; mi++)
            ldm_x4(afr[0][mi], aBase[b] + ((wi * 64 + mi * 16 + a_row) * STA + a_koff) * 2);
        #pragma unroll
        for (int njp = 0; njp < 2; njp++)
            ldm_x4(bfr[0][njp], bBase[b] + ((wj * 32 + njp * 16 + b_nrow) * STA + b_koff) * 2);

        #pragma unroll
        for (int kh = 0; kh < 5; kh++) {
            const int cur = kh & 1;
            if (kh < 4) {
                const int nxt = cur ^ 1, ko = (kh + 1) * 16;
                #pragma unroll
                for (int mi = 0; mi < 4; mi++)
                    ldm_x4(afr[nxt][mi],
                           aBase[b] + ((wi * 64 + mi * 16 + a_row) * STA + ko + a_koff) * 2);
                #pragma unroll
                for (int njp = 0; njp < 2; njp++)
                    ldm_x4(bfr[nxt][njp],
                           bBase[b] + ((wj * 32 + njp * 16 + b_nrow) * STA + ko + b_koff) * 2);
            }
            #pragma unroll
            for (int mi = 0; mi < 4; mi++)
                #pragma unroll
                for (int nj = 0; nj < 4; nj++)
                    mma_bf16(acc[mi][nj], afr[cur][mi],
                             bfr[cur][nj >> 1][(nj & 1) * 2 + 0],
                             bfr[cur][nj >> 1][(nj & 1) * 2 + 1]);
        }
    }

    // ---------------- epilogue: RBF + alpha, fused ----------------
    const int r0 = lane >> 2;
    const int c0 = (lane & 3) * 2;
    float po[8][4];
    #pragma unroll
    for (int i = 0; i < 8; i++)
        #pragma unroll
        for (int c = 0; c < 4; c++) po[i][c] = 0.f;

    #pragma unroll
    for (int mi = 0; mi < 4; mi++)
        #pragma unroll
        for (int nj = 0; nj < 4; nj++)
            #pragma unroll
            for (int e = 0; e < 4; e++) {
                int h = e >> 1;
                int rowl = wi * 64 + mi * 16 + r0 + h * 8;
                int coll = wj * 32 + nj * 8 + c0 + (e & 1);
                float d2 = f2s[rowl] + s2s[coll] - 2.0f * acc[mi][nj][e];
                float kv = __expf(-GAMMA * d2);
                float4 al = als[coll];
                po[mi * 2 + h][0] += kv * al.x;
                po[mi * 2 + h][1] += kv * al.y;
                po[mi * 2 + h][2] += kv * al.z;
                po[mi * 2 + h][3] += kv * al.w;
            }

    #pragma unroll
    for (int off = 1; off <= 2; off <<= 1)
        #pragma unroll
        for (int i = 0; i < 8; i++)
            #pragma unroll
            for (int c = 0; c < 4; c++)
                po[i][c] += __shfl_xor_sync(0xffffffffu, po[i][c], off);

    __syncthreads();   // all ldmatrix reads done before red overwrites buf A0

    if ((lane & 3) == 0) {
        #pragma unroll
        for (int i = 0; i < 8; i++) {
            int mi = i >> 1, h = i & 1;
            int rowl = wi * 64 + mi * 16 + r0 + h * 8;
            #pragma unroll
            for (int c = 0; c < 4; c++)
                red[(wj * TI + rowl) * 4 + c] = po[i][c];
        }
    }
    __syncthreads();

    for (int id = tid; id < TI * NCLS; id += 256) {
        int rowl = id >> 2, c = id & 3;
        float sum = red[(0 * TI + rowl) * 4 + c] + red[(1 * TI + rowl) * 4 + c]
                  + red[(2 * TI + rowl) * 4 + c] + red[(3 * TI + rowl) * 4 + c];
        g_part[(size_t)((ibase + rowl) * NCLS + c) * NJT + blockIdx.y] = sum;
    }
}

// ---------------------------------------------------------------------------
// combine: 16 lanes per output element read 64 consecutive partials
// (transposed layout -> fully coalesced), shfl-tree reduce.
// ---------------------------------------------------------------------------
__global__ void __launch_bounds__(256) combine_kernel(float* __restrict__ out)
{
    const int tid = threadIdx.x;
    const int i = blockIdx.x * 16 + (tid >> 4);
    const int sub = tid & 15;
    float s = 0.f;
    #pragma unroll
    for (int q = 0; q < 4; q++)
        s += g_part[(size_t)i * NJT + sub + q * 16];
    #pragma unroll
    for (int off = 8; off; off >>= 1) s += __shfl_xor_sync(0xffffffffu, s, off);
    if (sub == 0) out[i] = s;
}

// ---------------------------------------------------------------------------
extern "C" void kernel_launch(void* const* d_in, const int* in_sizes, int n_in,
                              void* d_out, int out_size)
{
    const float* x       = (const float*)d_in[0];
    const float* w1      = (const float*)d_in[1];
    const float* b1      = (const float*)d_in[2];
    const float* w2      = (const float*)d_in[3];
    const float* b2      = (const float*)d_in[4];
    const float* support = (const float*)d_in[5];
    const float* alpha   = (const float*)d_in[6];
    float* out = (float*)d_out;

    static bool attr_set = false;
    if (!attr_set) {
        cudaFuncSetAttribute(gemm_mma, cudaFuncAttributeMaxDynamicSharedMemorySize, GEMM_SMEM);
        attr_set = true;
    }

    pre_kernel<<<CONV_BLOCKS + PREP_BLOCKS, 256>>>(x, w1, b1, w2, b2, support);
    gemm_mma<<<dim3(NIT, NJT), 256, GEMM_SMEM>>>(alpha);
    combine_kernel<<<NIMG * NCLS / 16, 256>>>(out);
}

// round 15
// speedup vs baseline: 1.0670x; 1.0670x over previous
#include <cuda_runtime.h>
#include <cuda_bf16.h>
#include <cstdint>

#define GAMMA 0.001f
#define NIMG 4096
#define MSUP 8192
#define KDIM 784
#define KPAD 800
#define NCLS 4

#define TI 128
#define TJ 128
#define KC 80
#define STA 88                 // padded smem row stride (elems): 176B, conflict-free
#define NSTAGE (KPAD / KC)     // 10
#define NJT (MSUP / TJ)        // 64
#define NIT (NIMG / TI)        // 32

#define CONV_BLOCKS (NIMG / 2)     // 2048 (2 images per block — R5/R11 proven)
#define PREP_BLOCKS (MSUP / 8)     // 1024

// ---- gemm dynamic smem layout (bytes) ----
#define BUF_BYTES (TI * STA * 2)         // 22528 per tile per buffer
#define OFF_A 0                          // 2 x 22528 = 45056
#define OFF_B 45056                      // 2 x 22528 = 45056
#define OFF_S2 90112                     // 512
#define OFF_F2 90624                     // 512
#define OFF_AL 91136                     // 2048
#define GEMM_SMEM 93184

// ---- device scratch (no allocs allowed) ----
__device__ __nv_bfloat16 g_featsB[NIMG * KPAD];
__device__ __nv_bfloat16 g_supB[MSUP * KPAD];
__device__ float g_s2[MSUP];
__device__ float g_f2[NIMG];
__device__ float g_part[NIMG * NCLS * NJT];   // transposed: [row*NCLS+c][jtile]

// ---------------------------------------------------------------------------
__device__ __forceinline__ uint32_t smem_u32(const void* p) {
    uint32_t a;
    asm("{ .reg .u64 t; cvta.to.shared.u64 t, %1; cvt.u32.u64 %0, t; }" : "=r"(a) : "l"(p));
    return a;
}
__device__ __forceinline__ void cp16(uint32_t smem, const void* gmem) {
    asm volatile("cp.async.cg.shared.global [%0], [%1], 16;" :: "r"(smem), "l"(gmem));
}
__device__ __forceinline__ void ldm_x4(uint32_t* r, uint32_t addr) {
    asm volatile("ldmatrix.sync.aligned.m8n8.x4.shared.b16 {%0,%1,%2,%3}, [%4];"
                 : "=r"(r[0]), "=r"(r[1]), "=r"(r[2]), "=r"(r[3]) : "r"(addr));
}
__device__ __forceinline__ void mma_bf16(float* d, const uint32_t* a, uint32_t b0, uint32_t b1) {
    asm volatile(
        "mma.sync.aligned.m16n8k16.row.col.f32.bf16.bf16.f32 "
        "{%0,%1,%2,%3}, {%4,%5,%6,%7}, {%8,%9}, {%0,%1,%2,%3};"
        : "+f"(d[0]), "+f"(d[1]), "+f"(d[2]), "+f"(d[3])
        : "r"(a[0]), "r"(a[1]), "r"(a[2]), "r"(a[3]), "r"(b0), "r"(b1));
}
__device__ __forceinline__ void ldw4(float* W, const float* base) {
    const float2* p = reinterpret_cast<const float2*>(base);
    float2 a = p[0], b = p[1];
    W[0] = a.x; W[1] = a.y; W[2] = b.x; W[3] = b.y;
}

// ---- packed f32x2 helpers (PTX ISA 8.6, sm_100+, plain feature set) ----
__device__ __forceinline__ uint64_t pk2(float lo, float hi) {
    uint64_t r;
    asm("mov.b64 %0, {%1, %2};" : "=l"(r) : "f"(lo), "f"(hi));
    return r;
}
__device__ __forceinline__ void upk2(float& lo, float& hi, uint64_t v) {
    asm("mov.b64 {%0, %1}, %2;" : "=f"(lo), "=f"(hi) : "l"(v));
}
__device__ __forceinline__ void fma2(uint64_t& d, uint64_t a, uint64_t b) {
    asm("fma.rn.f32x2 %0, %1, %2, %0;" : "+l"(d) : "l"(a), "l"(b));
}

// ---------------------------------------------------------------------------
// Merged preprocessing launch:
//   blocks [0, CONV_BLOCKS)            : conv pipeline (2 images/block)
//   blocks [CONV_BLOCKS, +PREP_BLOCKS) : support bf16 conversion + s2
// conv2 uses packed fma.rn.f32x2: the two sxx pool-quadrants ride one f32x2
// lane pair -> 18 FFMA2 instead of 36 FFMA per (ic, py).
// ---------------------------------------------------------------------------
__global__ void __launch_bounds__(256, 3) pre_kernel(
    const float* __restrict__ x,
    const float* __restrict__ w1, const float* __restrict__ b1,
    const float* __restrict__ w2, const float* __restrict__ b2,
    const float* __restrict__ support)
{
    const int tid = threadIdx.x;

    if (blockIdx.x >= CONV_BLOCKS) {
        int row = (blockIdx.x - CONV_BLOCKS) * 8 + (tid >> 5);
        int lane = tid & 31;
        const float* src = support + (size_t)row * KDIM;
        __nv_bfloat16* dst = g_supB + (size_t)row * KPAD;
        float s = 0.f;
        for (int k = lane; k < KDIM; k += 32) {
            __nv_bfloat16 b = __float2bfloat16(src[k]);
            dst[k] = b;
            float v = __bfloat162float(b);
            s += v * v;
        }
        if (lane < KPAD - KDIM) dst[KDIM + lane] = __float2bfloat16(0.f);
        #pragma unroll
        for (int off = 16; off; off >>= 1) s += __shfl_xor_sync(0xffffffffu, s, off);
        if (lane == 0) g_s2[row] = s;
        return;
    }

    __shared__ float sx[2][900];          // 30x30 padded (+1)
    __shared__ float sp1[2][2048];        // 8 x 16x16 padded (+1)
    __shared__ float sw1[72], sb1[8], sw2[1152], sb2[16];
    __shared__ float sred[2][4];

    const int img = tid >> 7;
    const int t = tid & 127;
    const int n = blockIdx.x * 2 + img;

    for (int i = tid; i < 1800; i += 256) ((float*)sx)[i] = 0.f;
    for (int i = tid; i < 4096; i += 256) ((float*)sp1)[i] = 0.f;
    for (int i = tid; i < 72; i += 256) sw1[i] = w1[i];
    if (tid < 8) sb1[tid] = b1[tid];
    for (int i = tid; i < 1152; i += 256) sw2[i] = w2[i];
    if (tid < 16) sb2[tid] = b2[tid];
    __syncthreads();

    const float* xn = x + (size_t)n * 784;
    for (int i = t; i < 784; i += 128) {
        int yy = i / 28, xx = i % 28;
        sx[img][(yy + 1) * 30 + xx + 1] = xn[i];
    }
    __syncthreads();

    // ---- conv1 + relu + pool: thread = (c in 0..7, px in 0..13), scalar ----
    if (t < 112) {
        const int c = t & 7, px = t >> 3;
        float w[9];
        #pragma unroll
        for (int k = 0; k < 9; k++) w[k] = sw1[c * 9 + k];
        const float bb = sb1[c];
        const float* sxi = sx[img];
        float W[4][4];
        #pragma unroll
        for (int py = 0; py < 14; py++) {
            if (py == 0) {
                #pragma unroll
                for (int r = 0; r < 4; r++)
                    ldw4(W[r], sxi + r * 30 + 2 * px);
            } else {
                #pragma unroll
                for (int cc = 0; cc < 4; cc++) { W[0][cc] = W[2][cc]; W[1][cc] = W[3][cc]; }
                #pragma unroll
                for (int r = 2; r < 4; r++)
                    ldw4(W[r], sxi + (2 * py + r) * 30 + 2 * px);
            }
            float m = 0.f;
            #pragma unroll
            for (int sy = 0; sy < 2; sy++)
                #pragma unroll
                for (int sxx = 0; sxx < 2; sxx++) {
                    float acc = bb;
                    #pragma unroll
                    for (int dy = 0; dy < 3; dy++)
                        #pragma unroll
                        for (int dx = 0; dx < 3; dx++)
                            acc += w[dy * 3 + dx] * W[sy + dy][sxx + dx];
                    m = fmaxf(m, fmaxf(acc, 0.f));
                }
            sp1[img][c * 256 + (py + 1) * 16 + px + 1] = m;
        }
    }
    __syncthreads();

    // ---- conv2 + relu + pool: thread = (c 0..15, px 0..6), f32x2 packed ----
    float sq = 0.f;
    if (t < 112) {
        const int px = t % 7, c = t / 7;
        const float bb = sb2[c];
        uint64_t acc2[7][2];                 // [py][sy] = (quad sxx=0, quad sxx=1)
        #pragma unroll
        for (int py = 0; py < 7; py++) {
            acc2[py][0] = pk2(bb, bb);
            acc2[py][1] = pk2(0.f, 0.f);     // sy=1 half gets bias once (via sy=0)
        }

        #pragma unroll
        for (int ic = 0; ic < 8; ic++) {
            uint64_t w2p[9];
            #pragma unroll
            for (int k = 0; k < 9; k++) {
                float wv = sw2[c * 72 + ic * 9 + k];
                w2p[k] = pk2(wv, wv);
            }
            const float* sp = sp1[img] + ic * 256;
            uint64_t Wp[4][3];               // [row][dx] = (W[row][dx], W[row][dx+1])
            #pragma unroll
            for (int py = 0; py < 7; py++) {
                if (py == 0) {
                    #pragma unroll
                    for (int r = 0; r < 4; r++) {
                        const float2* rp = (const float2*)(sp + r * 16 + 2 * px);
                        float2 a = rp[0], b = rp[1];
                        Wp[r][0] = pk2(a.x, a.y);
                        Wp[r][1] = pk2(a.y, b.x);
                        Wp[r][2] = pk2(b.x, b.y);
                    }
                } else {
                    #pragma unroll
                    for (int d = 0; d < 3; d++) { Wp[0][d] = Wp[2][d]; Wp[1][d] = Wp[3][d]; }
                    #pragma unroll
                    for (int r = 2; r < 4; r++) {
                        const float2* rp = (const float2*)(sp + (2 * py + r) * 16 + 2 * px);
                        float2 a = rp[0], b = rp[1];
                        Wp[r][0] = pk2(a.x, a.y);
                        Wp[r][1] = pk2(a.y, b.x);
                        Wp[r][2] = pk2(b.x, b.y);
                    }
                }
                #pragma unroll
                for (int sy = 0; sy < 2; sy++)
                    #pragma unroll
                    for (int dy = 0; dy < 3; dy++)
                        #pragma unroll
                        for (int dx = 0; dx < 3; dx++)
                            fma2(acc2[py][sy], w2p[dy * 3 + dx], Wp[sy + dy][dx]);
            }
        }

        __nv_bfloat16* fdst = g_featsB + (size_t)n * KPAD + c * 49 + px;
        #pragma unroll
        for (int py = 0; py < 7; py++) {
            float q00, q01, q10, q11;
            upk2(q00, q01, acc2[py][0]);
            upk2(q10, q11, acc2[py][1]);
            q10 += bb; q11 += bb;            // sy=1 half bias
            float m = fmaxf(fmaxf(fmaxf(q00, q01), fmaxf(q10, q11)), 0.f);
            __nv_bfloat16 bv = __float2bfloat16(m);
            fdst[py * 7] = bv;
            float fv = __bfloat162float(bv);
            sq += fv * fv;
        }
    }
    if (t < KPAD - KDIM)
        g_featsB[(size_t)n * KPAD + KDIM + t] = __float2bfloat16(0.f);

    // f2 block reduction (per image: 4 warps)
    #pragma unroll
    for (int off = 16; off; off >>= 1) sq += __shfl_xor_sync(0xffffffffu, sq, off);
    if ((t & 31) == 0) sred[img][(t >> 5) & 3] = sq;
    __syncthreads();
    if (t == 0) g_f2[n] = sred[img][0] + sred[img][1] + sred[img][2] + sred[img][3];
}

// ---------------------------------------------------------------------------
// bf16 mma.sync fused GEMM (R9/R11-proven): 128x128 CTA, KC=80, 10 stages,
// 2 smem buffers, register double-buffered fragments, 1 sync/stage.
// Partial store transposed: g_part[(row*NCLS+c)*NJT + jtile].
// ---------------------------------------------------------------------------
__global__ void __launch_bounds__(256, 2) gemm_mma(const float* __restrict__ alpha)
{
    extern __shared__ char dsm[];
    float* s2s = (float*)(dsm + OFF_S2);
    float* f2s = (float*)(dsm + OFF_F2);
    float4* als = (float4*)(dsm + OFF_AL);
    float* red = (float*)(dsm + OFF_A);   // reused after mainloop

    const int tid = threadIdx.x;
    const int lane = tid & 31, wid = tid >> 5;
    const int wi = wid >> 2;        // 0..1 : 64-row slice
    const int wj = wid & 3;         // 0..3 : 32-col slice
    const int ibase = blockIdx.x * TI;
    const int jbase = blockIdx.y * TJ;

    if (tid < TI) f2s[tid] = g_f2[ibase + tid];
    if (tid < TJ) {
        s2s[tid] = g_s2[jbase + tid];
        als[tid] = ((const float4*)alpha)[jbase + tid];
    }

    uint32_t aBase[2], bBase[2];
    #pragma unroll
    for (int b = 0; b < 2; b++) {
        aBase[b] = smem_u32(dsm + OFF_A + b * BUF_BYTES);
        bBase[b] = smem_u32(dsm + OFF_B + b * BUF_BYTES);
    }
    const __nv_bfloat16* gA = g_featsB + (size_t)ibase * KPAD;
    const __nv_bfloat16* gB = g_supB + (size_t)jbase * KPAD;

    float acc[4][4][4];
    #pragma unroll
    for (int mi = 0; mi < 4; mi++)
        #pragma unroll
        for (int nj = 0; nj < 4; nj++)
            #pragma unroll
            for (int e = 0; e < 4; e++) acc[mi][nj][e] = 0.f;

    auto prefetch = [&](int s, int b) {
        #pragma unroll
        for (int tcnt = 0; tcnt < 5; tcnt++) {
            int id = tid + tcnt * 256;
            int r = id / 10, c = id % 10;
            cp16(aBase[b] + (r * STA + c * 8) * 2, gA + (size_t)r * KPAD + s * KC + c * 8);
        }
        #pragma unroll
        for (int tcnt = 0; tcnt < 5; tcnt++) {
            int id = tid + tcnt * 256;
            int r = id / 10, c = id % 10;
            cp16(bBase[b] + (r * STA + c * 8) * 2, gB + (size_t)r * KPAD + s * KC + c * 8);
        }
        asm volatile("cp.async.commit_group;" ::: "memory");
    };

    prefetch(0, 0);

    const int a_row = (lane & 15);
    const int a_koff = (lane >> 4) * 8;
    const int b_nrow = ((lane >> 4) & 1) * 8 + (lane & 7);
    const int b_koff = ((lane >> 3) & 1) * 8;

    uint32_t afr[2][4][4], bfr[2][2][4];

    for (int s = 0; s < NSTAGE; s++) {
        asm volatile("cp.async.wait_group 0;" ::: "memory");
        __syncthreads();
        if (s + 1 < NSTAGE) prefetch(s + 1, (s + 1) & 1);

        const int b = s & 1;

        #pragma unroll
        for (int mi = 0; mi < 4; mi++)
            ldm_x4(afr[0][mi], aBase[b] + ((wi * 64 + mi * 16 + a_row) * STA + a_koff) * 2);
        #pragma unroll
        for (int njp = 0; njp < 2; njp++)
            ldm_x4(bfr[0][njp], bBase[b] + ((wj * 32 + njp * 16 + b_nrow) * STA + b_koff) * 2);

        #pragma unroll
        for (int kh = 0; kh < 5; kh++) {
            const int cur = kh & 1;
            if (kh < 4) {
                const int nxt = cur ^ 1, ko = (kh + 1) * 16;
                #pragma unroll
                for (int mi = 0; mi < 4; mi++)
                    ldm_x4(afr[nxt][mi],
                           aBase[b] + ((wi * 64 + mi * 16 + a_row) * STA + ko + a_koff) * 2);
                #pragma unroll
                for (int njp = 0; njp < 2; njp++)
                    ldm_x4(bfr[nxt][njp],
                           bBase[b] + ((wj * 32 + njp * 16 + b_nrow) * STA + ko + b_koff) * 2);
            }
            #pragma unroll
            for (int mi = 0; mi < 4; mi++)
                #pragma unroll
                for (int nj = 0; nj < 4; nj++)
                    mma_bf16(acc[mi][nj], afr[cur][mi],
                             bfr[cur][nj >> 1][(nj & 1) * 2 + 0],
                             bfr[cur][nj >> 1][(nj & 1) * 2 + 1]);
        }
    }

    // ---------------- epilogue: RBF + alpha, fused ----------------
    const int r0 = lane >> 2;
    const int c0 = (lane & 3) * 2;
    float po[8][4];
    #pragma unroll
    for (int i = 0; i < 8; i++)
        #pragma unroll
        for (int c = 0; c < 4; c++) po[i][c] = 0.f;

    #pragma unroll
    for (int mi = 0; mi < 4; mi++)
        #pragma unroll
        for (int nj = 0; nj < 4; nj++)
            #pragma unroll
            for (int e = 0; e < 4; e++) {
                int h = e >> 1;
                int rowl = wi * 64 + mi * 16 + r0 + h * 8;
                int coll = wj * 32 + nj * 8 + c0 + (e & 1);
                float d2 = f2s[rowl] + s2s[coll] - 2.0f * acc[mi][nj][e];
                float kv = __expf(-GAMMA * d2);
                float4 al = als[coll];
                po[mi * 2 + h][0] += kv * al.x;
                po[mi * 2 + h][1] += kv * al.y;
                po[mi * 2 + h][2] += kv * al.z;
                po[mi * 2 + h][3] += kv * al.w;
            }

    #pragma unroll
    for (int off = 1; off <= 2; off <<= 1)
        #pragma unroll
        for (int i = 0; i < 8; i++)
            #pragma unroll
            for (int c = 0; c < 4; c++)
                po[i][c] += __shfl_xor_sync(0xffffffffu, po[i][c], off);

    __syncthreads();   // all ldmatrix reads done before red overwrites buf A0

    if ((lane & 3) == 0) {
        #pragma unroll
        for (int i = 0; i < 8; i++) {
            int mi = i >> 1, h = i & 1;
            int rowl = wi * 64 + mi * 16 + r0 + h * 8;
            #pragma unroll
            for (int c = 0; c < 4; c++)
                red[(wj * TI + rowl) * 4 + c] = po[i][c];
        }
    }
    __syncthreads();

    for (int id = tid; id < TI * NCLS; id += 256) {
        int rowl = id >> 2, c = id & 3;
        float sum = red[(0 * TI + rowl) * 4 + c] + red[(1 * TI + rowl) * 4 + c]
                  + red[(2 * TI + rowl) * 4 + c] + red[(3 * TI + rowl) * 4 + c];
        g_part[(size_t)((ibase + rowl) * NCLS + c) * NJT + blockIdx.y] = sum;
    }
}

// ---------------------------------------------------------------------------
// combine: 16 lanes per output element read 64 consecutive partials
// (transposed layout -> fully coalesced), shfl-tree reduce.
// ---------------------------------------------------------------------------
__global__ void __launch_bounds__(256) combine_kernel(float* __restrict__ out)
{
    const int tid = threadIdx.x;
    const int i = blockIdx.x * 16 + (tid >> 4);
    const int sub = tid & 15;
    float s = 0.f;
    #pragma unroll
    for (int q = 0; q < 4; q++)
        s += g_part[(size_t)i * NJT + sub + q * 16];
    #pragma unroll
    for (int off = 8; off; off >>= 1) s += __shfl_xor_sync(0xffffffffu, s, off);
    if (sub == 0) out[i] = s;
}

// ---------------------------------------------------------------------------
extern "C" void kernel_launch(void* const* d_in, const int* in_sizes, int n_in,
                              void* d_out, int out_size)
{
    const float* x       = (const float*)d_in[0];
    const float* w1      = (const float*)d_in[1];
    const float* b1      = (const float*)d_in[2];
    const float* w2      = (const float*)d_in[3];
    const float* b2      = (const float*)d_in[4];
    const float* support = (const float*)d_in[5];
    const float* alpha   = (const float*)d_in[6];
    float* out = (float*)d_out;

    static bool attr_set = false;
    if (!attr_set) {
        cudaFuncSetAttribute(gemm_mma, cudaFuncAttributeMaxDynamicSharedMemorySize, GEMM_SMEM);
        attr_set = true;
    }

    pre_kernel<<<CONV_BLOCKS + PREP_BLOCKS, 256>>>(x, w1, b1, w2, b2, support);
    gemm_mma<<<dim3(NIT, NJT), 256, GEMM_SMEM>>>(alpha);
    combine_kernel<<<NIMG * NCLS / 16, 256>>>(out);
}